// round 11
// baseline (speedup 1.0000x reference)
#include <cuda_runtime.h>
#include <cuda_fp16.h>
#include <mma.h>
using namespace nvcuda;

#define NN      100000
#define ET_MAX  1700000
#define NEG     0.2f
#define EPSV    1e-16f
#define NB      98              // ceil(NN/1024)

// ---------------- scratch ----------------------------------------------------
__device__ __align__(128) __half g_h1h[NN * 64];   // h1 [N,64] fp16 (1 line/row)
__device__ float4 g_as1[NN];
__device__ float4 g_ad1[NN];
__device__ int    g_cnt[NN];
__device__ int    g_rp[NN + 1];
__device__ int    g_fill[NN];
__device__ int    g_csr[ET_MAX];
__device__ int    g_bsum[NB];
__device__ int    g_arrive;
__device__ float2 g_sh2[NN];          // packed {a_src2, h2}
__device__ float  g_ad2[NN];

__device__ __forceinline__ float lrelu(float a) { return a > 0.f ? a : NEG * a; }

// ---------------- zero -------------------------------------------------------
__global__ void k_zero() {
    int i = blockIdx.x * blockDim.x + threadIdx.x;
    if (i < NN) g_cnt[i] = 1;          // self-loop pre-counted
    if (i == 0) g_arrive = 0;
}

// ---------------- histogram (4 edges/thread, full grid) -----------------------
__global__ void k_hist(const int* __restrict__ ei, int E) {
    int i0 = (blockIdx.x * blockDim.x + threadIdx.x) * 4;
    if (i0 >= E) return;
    int4 d4 = *(const int4*)(ei + E + i0);
    atomicAdd(&g_cnt[d4.x], 1);
    atomicAdd(&g_cnt[d4.y], 1);
    atomicAdd(&g_cnt[d4.z], 1);
    atomicAdd(&g_cnt[d4.w], 1);
}

// ---------------- fused scan: block sums + grid barrier + rp/fill -------------
__global__ void k_rpf(int etot) {
    __shared__ int sh[1024];
    __shared__ int sboff;
    int b = blockIdx.x, t = threadIdx.x, i = b * 1024 + t;
    int v = (i < NN) ? g_cnt[i] : 0;
    sh[t] = v;
    __syncthreads();
    for (int off = 1; off < 1024; off <<= 1) {
        int cur = sh[t];
        int u = (t >= off) ? sh[t - off] : 0;
        __syncthreads();
        sh[t] = cur + u;
        __syncthreads();
    }
    if (t == 1023) {
        g_bsum[b] = sh[1023];
        __threadfence();
        atomicAdd(&g_arrive, 1);
    }
    if (t == 0) {
        while (atomicAdd(&g_arrive, 0) < NB) { }
        int run = 0;
        for (int k = 0; k < b; k++) run += g_bsum[k];
        sboff = run;
    }
    __syncthreads();
    if (i < NN) {
        int rp = sboff + sh[t] - v;        // exclusive
        g_rp[i]   = rp;
        g_fill[i] = rp + 1;                // slot 0 = self loop
        g_csr[rp] = i;
    }
    if (b == NB - 1 && t == 0) g_rp[NN] = etot;
}

// ---------------- scatter (4 edges/thread) ------------------------------------
__global__ void k_scatter(const int* __restrict__ ei, int E) {
    int i0 = (blockIdx.x * blockDim.x + threadIdx.x) * 4;
    if (i0 >= E) return;
    int4 s4 = *(const int4*)(ei + i0);
    int4 d4 = *(const int4*)(ei + E + i0);
    int p0 = atomicAdd(&g_fill[d4.x], 1);
    int p1 = atomicAdd(&g_fill[d4.y], 1);
    int p2 = atomicAdd(&g_fill[d4.z], 1);
    int p3 = atomicAdd(&g_fill[d4.w], 1);
    g_csr[p0] = s4.x;
    g_csr[p1] = s4.y;
    g_csr[p2] = s4.z;
    g_csr[p3] = s4.w;
}

// ---------------- GEMM1 via tf32 tensor cores + attn projections -------------
// One 64-node tile per block; 8 warps, each owns a 16x32 output slab.
#define NTILES ((NN + 63) / 64)
__global__ void k_gemm1(const float* __restrict__ x, const float* __restrict__ W,
                        const float* __restrict__ as, const float* __restrict__ ad) {
    __shared__ float sx[64 * 64];
    __shared__ float sW[64 * 64];
    __shared__ float sout[64 * 64];
    __shared__ float ss[64], sd[64];
    int t = threadIdx.x;
    int tile = blockIdx.x;
    {
        const float4* wg = (const float4*)W;
        for (int i = t; i < 1024; i += 256) ((float4*)sW)[i] = wg[i];
        const float4* xg = (const float4*)x;
        int base4 = tile * 1024;
#pragma unroll
        for (int r = 0; r < 4; r++) {
            int idx = t + r * 256;
            int g = base4 + idx;
            ((float4*)sx)[idx] = (g < NN * 16) ? xg[g] : make_float4(0.f, 0.f, 0.f, 0.f);
        }
        if (t < 64) { ss[t] = as[t]; sd[t] = ad[t]; }
    }
    __syncthreads();

    int w = t >> 5;
    int wr = w >> 1, wc = w & 1;       // row tile 0..3 (16 rows), col half 0..1 (32 cols)
    wmma::fragment<wmma::accumulator, 16, 16, 8, float> c0, c1;
    wmma::fill_fragment(c0, 0.f);
    wmma::fill_fragment(c1, 0.f);
    wmma::fragment<wmma::matrix_a, 16, 16, 8, wmma::precision::tf32, wmma::row_major> af;
    wmma::fragment<wmma::matrix_b, 16, 16, 8, wmma::precision::tf32, wmma::row_major> b0, b1;
#pragma unroll
    for (int k = 0; k < 64; k += 8) {
        wmma::load_matrix_sync(af, sx + (wr * 16) * 64 + k, 64);
#pragma unroll
        for (int i = 0; i < af.num_elements; i++) af.x[i] = wmma::__float_to_tf32(af.x[i]);
        wmma::load_matrix_sync(b0, sW + k * 64 + wc * 32, 64);
        wmma::load_matrix_sync(b1, sW + k * 64 + wc * 32 + 16, 64);
#pragma unroll
        for (int i = 0; i < b0.num_elements; i++) {
            b0.x[i] = wmma::__float_to_tf32(b0.x[i]);
            b1.x[i] = wmma::__float_to_tf32(b1.x[i]);
        }
        wmma::mma_sync(c0, af, b0, c0);
        wmma::mma_sync(c1, af, b1, c1);
    }
    wmma::store_matrix_sync(sout + (wr * 16) * 64 + wc * 32,      c0, 64, wmma::mem_row_major);
    wmma::store_matrix_sync(sout + (wr * 16) * 64 + wc * 32 + 16, c1, 64, wmma::mem_row_major);
    __syncthreads();

    // epilogue: thread = 4 rows x 4 cols from sout
    int ci = t & 15, rgl = t >> 4;
    int n0 = tile * 64 + rgl * 4;
#pragma unroll
    for (int r = 0; r < 4; r++) {
        int n = n0 + r;
        if (n >= NN) break;
        float4 a = *(const float4*)(sout + (rgl * 4 + r) * 64 + 4 * ci);
        __half2 p0 = __floats2half2_rn(a.x, a.y);
        __half2 p1 = __floats2half2_rn(a.z, a.w);
        __half2* hp = (__half2*)(g_h1h + (size_t)n * 64 + 4 * ci);
        hp[0] = p0; hp[1] = p1;
        float sv = a.x * ss[4 * ci] + a.y * ss[4 * ci + 1]
                 + a.z * ss[4 * ci + 2] + a.w * ss[4 * ci + 3];
        float dv = a.x * sd[4 * ci] + a.y * sd[4 * ci + 1]
                 + a.z * sd[4 * ci + 2] + a.w * sd[4 * ci + 3];
#pragma unroll
        for (int off = 1; off <= 2; off <<= 1) {
            sv += __shfl_xor_sync(0xffffffffu, sv, off);
            dv += __shfl_xor_sync(0xffffffffu, dv, off);
        }
        if ((ci & 3) == 0) {
            int head = ci >> 2;
            ((float*)&g_as1[n])[head] = sv;
            ((float*)&g_ad1[n])[head] = dv;
        }
    }
}

// ---------------- layer1 aggregation: warp per dst ----------------------------
__global__ void k_agg1(const float* __restrict__ b1, const float* __restrict__ W2,
                       const float* __restrict__ as2p, const float* __restrict__ ad2p) {
    __shared__ int   ssrc[8][32];
    __shared__ float seT[8][4][33];
    int lane = threadIdx.x & 31, w = threadIdx.x >> 5;
    int d = blockIdx.x * 8 + w;
    if (d >= NN) return;
    int base = g_rp[d];
    int deg  = g_rp[d + 1] - base;
    float4 ad = g_ad1[d];

    int hh = lane >> 3;
    float acc0 = 0.f, acc1 = 0.f;
    float d0 = 0.f, d1 = 0.f, d2 = 0.f, d3 = 0.f;

    for (int chunk = 0; chunk < deg; chunk += 32) {
        int i = chunk + lane;
        int s = 0;
        float e0 = 0.f, e1 = 0.f, e2 = 0.f, e3 = 0.f;
        if (i < deg) {
            s = g_csr[base + i];
            float4 a = g_as1[s];
            e0 = __expf(lrelu(a.x + ad.x)); d0 += e0;
            e1 = __expf(lrelu(a.y + ad.y)); d1 += e1;
            e2 = __expf(lrelu(a.z + ad.z)); d2 += e2;
            e3 = __expf(lrelu(a.w + ad.w)); d3 += e3;
        }
        __syncwarp();
        ssrc[w][lane] = s;
        seT[w][0][lane] = e0; seT[w][1][lane] = e1;
        seT[w][2][lane] = e2; seT[w][3][lane] = e3;
        __syncwarp();
        int cnt = deg - chunk; if (cnt > 32) cnt = 32;
        int j = 0;
        for (; j + 8 <= cnt; j += 8) {
            __half2 v[8]; float ew[8];
#pragma unroll
            for (int k = 0; k < 8; k++) {
                int sj = ssrc[w][j + k];
                v[k]  = ((const __half2*)(g_h1h + (size_t)sj * 64))[lane];
                ew[k] = seT[w][hh][j + k];
            }
#pragma unroll
            for (int k = 0; k < 8; k++) {
                float2 f = __half22float2(v[k]);
                acc0 = fmaf(f.x, ew[k], acc0);
                acc1 = fmaf(f.y, ew[k], acc1);
            }
        }
        for (; j < cnt; j++) {
            int sj = ssrc[w][j];
            __half2 vv = ((const __half2*)(g_h1h + (size_t)sj * 64))[lane];
            float ew = seT[w][hh][j];
            float2 f = __half22float2(vv);
            acc0 = fmaf(f.x, ew, acc0);
            acc1 = fmaf(f.y, ew, acc1);
        }
    }
#pragma unroll
    for (int off = 16; off; off >>= 1) {
        d0 += __shfl_xor_sync(0xffffffffu, d0, off);
        d1 += __shfl_xor_sync(0xffffffffu, d1, off);
        d2 += __shfl_xor_sync(0xffffffffu, d2, off);
        d3 += __shfl_xor_sync(0xffffffffu, d3, off);
    }

    float den = (hh == 0 ? d0 : hh == 1 ? d1 : hh == 2 ? d2 : d3) + EPSV;
    float2 bb = ((const float2*)b1)[lane];
    float2 ww = ((const float2*)W2)[lane];
    float v0 = acc0 / den + bb.x;
    float v1 = acc1 / den + bb.y;
    v0 = v0 > 0.f ? v0 : (__expf(v0) - 1.f);
    v1 = v1 > 0.f ? v1 : (__expf(v1) - 1.f);
    float h2 = v0 * ww.x + v1 * ww.y;
#pragma unroll
    for (int off = 16; off; off >>= 1) h2 += __shfl_xor_sync(0xffffffffu, h2, off);
    if (lane == 0) {
        g_sh2[d] = make_float2(h2 * as2p[0], h2);
        g_ad2[d] = h2 * ad2p[0];
    }
}

// ---------------- layer2 aggregation + final output ---------------------------
__global__ void k_agg2(float* __restrict__ out, const float* __restrict__ b2) {
    int lane = threadIdx.x & 31, warp = threadIdx.x >> 5;
    int d = blockIdx.x * 8 + warp;
    if (d >= NN) return;
    int base = g_rp[d];
    int deg  = g_rp[d + 1] - base;
    float adv = g_ad2[d];

    float num = 0.f, den = 0.f;
    for (int i = lane; i < deg; i += 32) {
        int s = g_csr[base + i];
        float2 sh = g_sh2[s];
        float e = __expf(lrelu(sh.x + adv));
        num = fmaf(e, sh.y, num);
        den += e;
    }
#pragma unroll
    for (int off = 16; off; off >>= 1) {
        num += __shfl_xor_sync(0xffffffffu, num, off);
        den += __shfl_xor_sync(0xffffffffu, den, off);
    }
    if (lane == 0) out[d] = num / (den + EPSV) + b2[0];
}

// ---------------- launch -----------------------------------------------------
extern "C" void kernel_launch(void* const* d_in, const int* in_sizes, int n_in,
                              void* d_out, int out_size) {
    const float* x    = (const float*)d_in[0];
    const int*   ei   = (const int*)d_in[1];
    const float* W1   = (const float*)d_in[2];
    const float* as1  = (const float*)d_in[3];
    const float* ad1  = (const float*)d_in[4];
    const float* b1   = (const float*)d_in[5];
    const float* W2   = (const float*)d_in[6];
    const float* as2  = (const float*)d_in[7];
    const float* ad2  = (const float*)d_in[8];
    const float* b2   = (const float*)d_in[9];
    float*       out  = (float*)d_out;

    int E    = in_sizes[1] / 2;
    int etot = E + NN;
    int eb4  = (E / 4 + 255) / 256;

    k_zero   <<<(NN + 255) / 256, 256>>>();                  // 0
    k_hist   <<<eb4, 256>>>(ei, E);                          // 1
    k_rpf    <<<NB, 1024>>>(etot);                           // 2
    k_gemm1  <<<NTILES, 256>>>(x, W1, as1, ad1);             // 3
    k_scatter<<<eb4, 256>>>(ei, E);                          // 4
    k_agg1   <<<NN / 8, 256>>>(b1, W2, as2, ad2);            // 5
    k_agg2   <<<NN / 8, 256>>>(out, b2);                     // 6
}

// round 12
// speedup vs baseline: 1.1012x; 1.1012x over previous
#include <cuda_runtime.h>
#include <cuda_fp16.h>

#define NN      100000
#define ET_MAX  1700000
#define NEG     0.2f
#define EPSV    1e-16f
#define NB      98              // ceil(NN/1024)

// ---------------- scratch ----------------------------------------------------
__device__ __align__(128) __half g_h1h[NN * 64];   // h1 [N,64] fp16 (1 line/row)
__device__ float4 g_as1[NN];
__device__ float4 g_ad1[NN];
__device__ int    g_cnt[NN];          // must be 0 at call entry; rpf resets it
__device__ int    g_rp[NN + 1];
__device__ int    g_fill[NN];
__device__ int    g_csr[ET_MAX];
__device__ int    g_bsum[NB];
__device__ int    g_arrive;           // must be 0 at call entry; scatter resets it
__device__ float2 g_sh2[NN];          // packed {a_src2, h2}
__device__ float  g_ad2[NN];

__device__ __forceinline__ float lrelu(float a) { return a > 0.f ? a : NEG * a; }

// ---------------- histogram (4 edges/thread, cnt base = 0) --------------------
__global__ void k_hist(const int* __restrict__ ei, int E) {
    int i0 = (blockIdx.x * blockDim.x + threadIdx.x) * 4;
    if (i0 >= E) return;
    int4 d4 = *(const int4*)(ei + E + i0);
    atomicAdd(&g_cnt[d4.x], 1);
    atomicAdd(&g_cnt[d4.y], 1);
    atomicAdd(&g_cnt[d4.z], 1);
    atomicAdd(&g_cnt[d4.w], 1);
}

// ---------------- fused scan: block sums + grid barrier + rp/fill -------------
// 98 blocks x 1024, all co-resident on 148 SMs. Adds +1 self-loop per node,
// resets g_cnt to 0 for the next call.
__global__ void k_rpf(int etot) {
    __shared__ int sh[1024];
    __shared__ int sboff;
    int b = blockIdx.x, t = threadIdx.x, i = b * 1024 + t;
    int v = 0;
    if (i < NN) { v = g_cnt[i] + 1; g_cnt[i] = 0; }
    sh[t] = v;
    __syncthreads();
    for (int off = 1; off < 1024; off <<= 1) {
        int cur = sh[t];
        int u = (t >= off) ? sh[t - off] : 0;
        __syncthreads();
        sh[t] = cur + u;
        __syncthreads();
    }
    if (t == 1023) {
        g_bsum[b] = sh[1023];
        __threadfence();
        atomicAdd(&g_arrive, 1);
    }
    if (t == 0) {
        while (atomicAdd(&g_arrive, 0) < NB) { }
        int run = 0;
        for (int k = 0; k < b; k++) run += g_bsum[k];
        sboff = run;
    }
    __syncthreads();
    if (i < NN) {
        int rp = sboff + sh[t] - v;        // exclusive
        g_rp[i]   = rp;
        g_fill[i] = rp + 1;                // slot 0 = self loop
        g_csr[rp] = i;
    }
    if (b == NB - 1 && t == 0) g_rp[NN] = etot;
}

// ---------------- scatter (4 edges/thread); resets arrive counter --------------
__global__ void k_scatter(const int* __restrict__ ei, int E) {
    int gid = blockIdx.x * blockDim.x + threadIdx.x;
    if (gid == 0) g_arrive = 0;            // rpf fully done by stream order
    int i0 = gid * 4;
    if (i0 >= E) return;
    int4 s4 = *(const int4*)(ei + i0);
    int4 d4 = *(const int4*)(ei + E + i0);
    int p0 = atomicAdd(&g_fill[d4.x], 1);
    int p1 = atomicAdd(&g_fill[d4.y], 1);
    int p2 = atomicAdd(&g_fill[d4.z], 1);
    int p3 = atomicAdd(&g_fill[d4.w], 1);
    g_csr[p0] = s4.x;
    g_csr[p1] = s4.y;
    g_csr[p2] = s4.z;
    g_csr[p3] = s4.w;
}

// ---------------- GEMM1 + attention projections, register-tiled (R8) ----------
// 64 nodes per tile; thread = 4 rows x 4 cols micro-tile. Persistent.
#define GEMM_BLOCKS 1184
#define NTILES      ((NN + 63) / 64)
__global__ void k_gemm1(const float* __restrict__ x, const float* __restrict__ W,
                        const float* __restrict__ as, const float* __restrict__ ad) {
    __shared__ float4 sW4[64 * 16];    // sW4[k*16+ci] = W[k][4ci..4ci+3]
    __shared__ float  sx[64 * 64];
    __shared__ float  ss[64], sd[64];
    int t = threadIdx.x;
    for (int i = t; i < 1024; i += 256) sW4[i] = ((const float4*)W)[i];
    if (t < 64) { ss[t] = as[t]; sd[t] = ad[t]; }
    int ci = t & 15, rgl = t >> 4;

    for (int tile = blockIdx.x; tile < NTILES; tile += GEMM_BLOCKS) {
        __syncthreads();
        {
            const float4* xg = (const float4*)x;
            int base4 = tile * 1024;
#pragma unroll
            for (int r = 0; r < 4; r++) {
                int idx = t + r * 256;
                int g = base4 + idx;
                ((float4*)sx)[idx] = (g < NN * 16) ? xg[g]
                                   : make_float4(0.f, 0.f, 0.f, 0.f);
            }
        }
        __syncthreads();

        const float* x0 = &sx[(rgl * 4 + 0) * 64];
        const float* x1 = &sx[(rgl * 4 + 1) * 64];
        const float* x2 = &sx[(rgl * 4 + 2) * 64];
        const float* x3 = &sx[(rgl * 4 + 3) * 64];
        float a0[4] = {0.f, 0.f, 0.f, 0.f};
        float a1[4] = {0.f, 0.f, 0.f, 0.f};
        float a2[4] = {0.f, 0.f, 0.f, 0.f};
        float a3[4] = {0.f, 0.f, 0.f, 0.f};
#pragma unroll
        for (int k = 0; k < 64; k += 4) {
            float4 xa = *(const float4*)(x0 + k);
            float4 xb = *(const float4*)(x1 + k);
            float4 xc = *(const float4*)(x2 + k);
            float4 xd = *(const float4*)(x3 + k);
#pragma unroll
            for (int kk = 0; kk < 4; kk++) {
                float4 wv = sW4[(k + kk) * 16 + ci];
                float va = (&xa.x)[kk], vb = (&xb.x)[kk];
                float vc = (&xc.x)[kk], vd = (&xd.x)[kk];
                a0[0] = fmaf(va, wv.x, a0[0]); a0[1] = fmaf(va, wv.y, a0[1]);
                a0[2] = fmaf(va, wv.z, a0[2]); a0[3] = fmaf(va, wv.w, a0[3]);
                a1[0] = fmaf(vb, wv.x, a1[0]); a1[1] = fmaf(vb, wv.y, a1[1]);
                a1[2] = fmaf(vb, wv.z, a1[2]); a1[3] = fmaf(vb, wv.w, a1[3]);
                a2[0] = fmaf(vc, wv.x, a2[0]); a2[1] = fmaf(vc, wv.y, a2[1]);
                a2[2] = fmaf(vc, wv.z, a2[2]); a2[3] = fmaf(vc, wv.w, a2[3]);
                a3[0] = fmaf(vd, wv.x, a3[0]); a3[1] = fmaf(vd, wv.y, a3[1]);
                a3[2] = fmaf(vd, wv.z, a3[2]); a3[3] = fmaf(vd, wv.w, a3[3]);
            }
        }
        int n0 = tile * 64 + rgl * 4;
        float* rows[4] = {a0, a1, a2, a3};
#pragma unroll
        for (int r = 0; r < 4; r++) {
            int n = n0 + r;
            if (n >= NN) break;
            float* a = rows[r];
            __half2 p0 = __floats2half2_rn(a[0], a[1]);
            __half2 p1 = __floats2half2_rn(a[2], a[3]);
            __half2* hp = (__half2*)(g_h1h + (size_t)n * 64 + 4 * ci);
            hp[0] = p0; hp[1] = p1;
            float sv = a[0] * ss[4 * ci] + a[1] * ss[4 * ci + 1]
                     + a[2] * ss[4 * ci + 2] + a[3] * ss[4 * ci + 3];
            float dv = a[0] * sd[4 * ci] + a[1] * sd[4 * ci + 1]
                     + a[2] * sd[4 * ci + 2] + a[3] * sd[4 * ci + 3];
#pragma unroll
            for (int off = 1; off <= 2; off <<= 1) {
                sv += __shfl_xor_sync(0xffffffffu, sv, off);
                dv += __shfl_xor_sync(0xffffffffu, dv, off);
            }
            if ((ci & 3) == 0) {
                int head = ci >> 2;
                ((float*)&g_as1[n])[head] = sv;
                ((float*)&g_ad1[n])[head] = dv;
            }
        }
    }
}

// ---------------- layer1 aggregation: warp per dst ----------------------------
__global__ void k_agg1(const float* __restrict__ b1, const float* __restrict__ W2,
                       const float* __restrict__ as2p, const float* __restrict__ ad2p) {
    __shared__ int   ssrc[8][32];
    __shared__ float seT[8][4][33];
    int lane = threadIdx.x & 31, w = threadIdx.x >> 5;
    int d = blockIdx.x * 8 + w;
    if (d >= NN) return;
    int base = g_rp[d];
    int deg  = g_rp[d + 1] - base;
    float4 ad = g_ad1[d];

    int hh = lane >> 3;
    float acc0 = 0.f, acc1 = 0.f;
    float d0 = 0.f, d1 = 0.f, d2 = 0.f, d3 = 0.f;

    for (int chunk = 0; chunk < deg; chunk += 32) {
        int i = chunk + lane;
        int s = 0;
        float e0 = 0.f, e1 = 0.f, e2 = 0.f, e3 = 0.f;
        if (i < deg) {
            s = g_csr[base + i];
            float4 a = g_as1[s];
            e0 = __expf(lrelu(a.x + ad.x)); d0 += e0;
            e1 = __expf(lrelu(a.y + ad.y)); d1 += e1;
            e2 = __expf(lrelu(a.z + ad.z)); d2 += e2;
            e3 = __expf(lrelu(a.w + ad.w)); d3 += e3;
        }
        __syncwarp();
        ssrc[w][lane] = s;
        seT[w][0][lane] = e0; seT[w][1][lane] = e1;
        seT[w][2][lane] = e2; seT[w][3][lane] = e3;
        __syncwarp();
        int cnt = deg - chunk; if (cnt > 32) cnt = 32;
        int j = 0;
        for (; j + 8 <= cnt; j += 8) {
            __half2 v[8]; float ew[8];
#pragma unroll
            for (int k = 0; k < 8; k++) {
                int sj = ssrc[w][j + k];
                v[k]  = ((const __half2*)(g_h1h + (size_t)sj * 64))[lane];
                ew[k] = seT[w][hh][j + k];
            }
#pragma unroll
            for (int k = 0; k < 8; k++) {
                float2 f = __half22float2(v[k]);
                acc0 = fmaf(f.x, ew[k], acc0);
                acc1 = fmaf(f.y, ew[k], acc1);
            }
        }
        for (; j < cnt; j++) {
            int sj = ssrc[w][j];
            __half2 vv = ((const __half2*)(g_h1h + (size_t)sj * 64))[lane];
            float ew = seT[w][hh][j];
            float2 f = __half22float2(vv);
            acc0 = fmaf(f.x, ew, acc0);
            acc1 = fmaf(f.y, ew, acc1);
        }
    }
#pragma unroll
    for (int off = 16; off; off >>= 1) {
        d0 += __shfl_xor_sync(0xffffffffu, d0, off);
        d1 += __shfl_xor_sync(0xffffffffu, d1, off);
        d2 += __shfl_xor_sync(0xffffffffu, d2, off);
        d3 += __shfl_xor_sync(0xffffffffu, d3, off);
    }

    float den = (hh == 0 ? d0 : hh == 1 ? d1 : hh == 2 ? d2 : d3) + EPSV;
    float2 bb = ((const float2*)b1)[lane];
    float2 ww = ((const float2*)W2)[lane];
    float v0 = acc0 / den + bb.x;
    float v1 = acc1 / den + bb.y;
    v0 = v0 > 0.f ? v0 : (__expf(v0) - 1.f);
    v1 = v1 > 0.f ? v1 : (__expf(v1) - 1.f);
    float h2 = v0 * ww.x + v1 * ww.y;
#pragma unroll
    for (int off = 16; off; off >>= 1) h2 += __shfl_xor_sync(0xffffffffu, h2, off);
    if (lane == 0) {
        g_sh2[d] = make_float2(h2 * as2p[0], h2);
        g_ad2[d] = h2 * ad2p[0];
    }
}

// ---------------- layer2 aggregation + final output ---------------------------
__global__ void k_agg2(float* __restrict__ out, const float* __restrict__ b2) {
    int lane = threadIdx.x & 31, warp = threadIdx.x >> 5;
    int d = blockIdx.x * 8 + warp;
    if (d >= NN) return;
    int base = g_rp[d];
    int deg  = g_rp[d + 1] - base;
    float adv = g_ad2[d];

    float num = 0.f, den = 0.f;
    for (int i = lane; i < deg; i += 32) {
        int s = g_csr[base + i];
        float2 sh = g_sh2[s];
        float e = __expf(lrelu(sh.x + adv));
        num = fmaf(e, sh.y, num);
        den += e;
    }
#pragma unroll
    for (int off = 16; off; off >>= 1) {
        num += __shfl_xor_sync(0xffffffffu, num, off);
        den += __shfl_xor_sync(0xffffffffu, den, off);
    }
    if (lane == 0) out[d] = num / (den + EPSV) + b2[0];
}

// ---------------- launch: fork gemm1 onto a side stream -----------------------
extern "C" void kernel_launch(void* const* d_in, const int* in_sizes, int n_in,
                              void* d_out, int out_size) {
    const float* x    = (const float*)d_in[0];
    const int*   ei   = (const int*)d_in[1];
    const float* W1   = (const float*)d_in[2];
    const float* as1  = (const float*)d_in[3];
    const float* ad1  = (const float*)d_in[4];
    const float* b1   = (const float*)d_in[5];
    const float* W2   = (const float*)d_in[6];
    const float* as2  = (const float*)d_in[7];
    const float* ad2  = (const float*)d_in[8];
    const float* b2   = (const float*)d_in[9];
    float*       out  = (float*)d_out;

    int E    = in_sizes[1] / 2;
    int etot = E + NN;
    int eb4  = (E / 4 + 255) / 256;

    // Fork: gemm1 runs on s2 concurrently with the CSR chain on the null stream.
    // Streams/events are created per call and intentionally not destroyed:
    // kernel_launch runs exactly twice (correctness + capture), and destroying
    // a stream mid-capture is illegal.
    cudaStream_t s2;
    cudaStreamCreate(&s2);
    cudaEvent_t eF, eG;
    cudaEventCreateWithFlags(&eF, cudaEventDisableTiming);
    cudaEventCreateWithFlags(&eG, cudaEventDisableTiming);

    cudaEventRecord(eF, 0);
    cudaStreamWaitEvent(s2, eF, 0);
    k_gemm1<<<GEMM_BLOCKS, 256, 0, s2>>>(x, W1, as1, ad1);
    cudaEventRecord(eG, s2);

    k_hist   <<<eb4, 256>>>(ei, E);
    k_rpf    <<<NB, 1024>>>(etot);
    k_scatter<<<eb4, 256>>>(ei, E);

    cudaStreamWaitEvent(0, eG, 0);
    k_agg1   <<<NN / 8, 256>>>(b1, W2, as2, ad2);
    k_agg2   <<<NN / 8, 256>>>(out, b2);
}

// round 13
// speedup vs baseline: 1.1299x; 1.0260x over previous
#include <cuda_runtime.h>
#include <cuda_fp16.h>

#define NN      100000
#define ET_MAX  1700000
#define NEG     0.2f
#define EPSV    1e-16f
#define NB      98              // ceil(NN/1024)

// ---------------- scratch ----------------------------------------------------
__device__ __align__(128) __half g_h1h[NN * 64];   // h1 [N,64] fp16 (1 line/row)
__device__ float4 g_as1[NN];
__device__ float4 g_ad1[NN];
__device__ int    g_cnt[NN];          // must be 0 at call entry; rpf resets it
__device__ int    g_rp[NN + 1];
__device__ int    g_rank[ET_MAX];     // per-edge rank within its dst row
__device__ int    g_csr[ET_MAX];
__device__ int    g_bsum[NB];
__device__ int    g_arrive;           // must be 0 at call entry; scatter resets it
__device__ float2 g_sh2[NN];          // packed {a_src2, h2}
__device__ float  g_ad2[NN];

__device__ __forceinline__ float lrelu(float a) { return a > 0.f ? a : NEG * a; }

// ---------------- histogram + rank capture (4 edges/thread) -------------------
__global__ void k_hist(const int* __restrict__ ei, int E) {
    int i0 = (blockIdx.x * blockDim.x + threadIdx.x) * 4;
    if (i0 >= E) return;
    int4 d4 = *(const int4*)(ei + E + i0);
    int r0 = atomicAdd(&g_cnt[d4.x], 1);
    int r1 = atomicAdd(&g_cnt[d4.y], 1);
    int r2 = atomicAdd(&g_cnt[d4.z], 1);
    int r3 = atomicAdd(&g_cnt[d4.w], 1);
    *(int4*)(g_rank + i0) = make_int4(r0, r1, r2, r3);
}

// ---------------- fused scan: block sums + grid barrier + rp ------------------
// 98 blocks x 1024, all co-resident on 148 SMs. Adds +1 self-loop per node,
// resets g_cnt to 0 for the next call, places self-loop at row start.
__global__ void k_rpf(int etot) {
    __shared__ int sh[1024];
    __shared__ int sboff;
    int b = blockIdx.x, t = threadIdx.x, i = b * 1024 + t;
    int v = 0;
    if (i < NN) { v = g_cnt[i] + 1; g_cnt[i] = 0; }
    sh[t] = v;
    __syncthreads();
    for (int off = 1; off < 1024; off <<= 1) {
        int cur = sh[t];
        int u = (t >= off) ? sh[t - off] : 0;
        __syncthreads();
        sh[t] = cur + u;
        __syncthreads();
    }
    if (t == 1023) {
        g_bsum[b] = sh[1023];
        __threadfence();
        atomicAdd(&g_arrive, 1);
    }
    if (t == 0) {
        while (atomicAdd(&g_arrive, 0) < NB) { }
        int run = 0;
        for (int k = 0; k < b; k++) run += g_bsum[k];
        sboff = run;
    }
    __syncthreads();
    if (i < NN) {
        int rp = sboff + sh[t] - v;        // exclusive
        g_rp[i]   = rp;
        g_csr[rp] = i;                     // slot 0 = self loop
    }
    if (b == NB - 1 && t == 0) g_rp[NN] = etot;
}

// ---------------- scatter: atomic-free via ranks (4 edges/thread) -------------
__global__ void k_scatter(const int* __restrict__ ei, int E) {
    int gid = blockIdx.x * blockDim.x + threadIdx.x;
    if (gid == 0) g_arrive = 0;            // rpf done by stream order
    int i0 = gid * 4;
    if (i0 >= E) return;
    int4 s4 = *(const int4*)(ei + i0);
    int4 d4 = *(const int4*)(ei + E + i0);
    int4 r4 = *(const int4*)(g_rank + i0);
    int p0 = g_rp[d4.x] + 1 + r4.x;
    int p1 = g_rp[d4.y] + 1 + r4.y;
    int p2 = g_rp[d4.z] + 1 + r4.z;
    int p3 = g_rp[d4.w] + 1 + r4.w;
    g_csr[p0] = s4.x;
    g_csr[p1] = s4.y;
    g_csr[p2] = s4.z;
    g_csr[p3] = s4.w;
}

// ---------------- GEMM1 + attention projections, register-tiled ---------------
// 64 nodes per tile; thread = 4 rows x 4 cols micro-tile. Persistent.
#define GEMM_BLOCKS 1184
#define NTILES      ((NN + 63) / 64)
__global__ void k_gemm1(const float* __restrict__ x, const float* __restrict__ W,
                        const float* __restrict__ as, const float* __restrict__ ad) {
    __shared__ float4 sW4[64 * 16];    // sW4[k*16+ci] = W[k][4ci..4ci+3]
    __shared__ float  sx[64 * 64];
    __shared__ float  ss[64], sd[64];
    int t = threadIdx.x;
    for (int i = t; i < 1024; i += 256) sW4[i] = ((const float4*)W)[i];
    if (t < 64) { ss[t] = as[t]; sd[t] = ad[t]; }
    int ci = t & 15, rgl = t >> 4;

    for (int tile = blockIdx.x; tile < NTILES; tile += GEMM_BLOCKS) {
        __syncthreads();
        {
            const float4* xg = (const float4*)x;
            int base4 = tile * 1024;
#pragma unroll
            for (int r = 0; r < 4; r++) {
                int idx = t + r * 256;
                int g = base4 + idx;
                ((float4*)sx)[idx] = (g < NN * 16) ? xg[g]
                                   : make_float4(0.f, 0.f, 0.f, 0.f);
            }
        }
        __syncthreads();

        const float* x0 = &sx[(rgl * 4 + 0) * 64];
        const float* x1 = &sx[(rgl * 4 + 1) * 64];
        const float* x2 = &sx[(rgl * 4 + 2) * 64];
        const float* x3 = &sx[(rgl * 4 + 3) * 64];
        float a0[4] = {0.f, 0.f, 0.f, 0.f};
        float a1[4] = {0.f, 0.f, 0.f, 0.f};
        float a2[4] = {0.f, 0.f, 0.f, 0.f};
        float a3[4] = {0.f, 0.f, 0.f, 0.f};
#pragma unroll
        for (int k = 0; k < 64; k += 4) {
            float4 xa = *(const float4*)(x0 + k);
            float4 xb = *(const float4*)(x1 + k);
            float4 xc = *(const float4*)(x2 + k);
            float4 xd = *(const float4*)(x3 + k);
#pragma unroll
            for (int kk = 0; kk < 4; kk++) {
                float4 wv = sW4[(k + kk) * 16 + ci];
                float va = (&xa.x)[kk], vb = (&xb.x)[kk];
                float vc = (&xc.x)[kk], vd = (&xd.x)[kk];
                a0[0] = fmaf(va, wv.x, a0[0]); a0[1] = fmaf(va, wv.y, a0[1]);
                a0[2] = fmaf(va, wv.z, a0[2]); a0[3] = fmaf(va, wv.w, a0[3]);
                a1[0] = fmaf(vb, wv.x, a1[0]); a1[1] = fmaf(vb, wv.y, a1[1]);
                a1[2] = fmaf(vb, wv.z, a1[2]); a1[3] = fmaf(vb, wv.w, a1[3]);
                a2[0] = fmaf(vc, wv.x, a2[0]); a2[1] = fmaf(vc, wv.y, a2[1]);
                a2[2] = fmaf(vc, wv.z, a2[2]); a2[3] = fmaf(vc, wv.w, a2[3]);
                a3[0] = fmaf(vd, wv.x, a3[0]); a3[1] = fmaf(vd, wv.y, a3[1]);
                a3[2] = fmaf(vd, wv.z, a3[2]); a3[3] = fmaf(vd, wv.w, a3[3]);
            }
        }
        int n0 = tile * 64 + rgl * 4;
        float* rows[4] = {a0, a1, a2, a3};
#pragma unroll
        for (int r = 0; r < 4; r++) {
            int n = n0 + r;
            if (n >= NN) break;
            float* a = rows[r];
            __half2 p0 = __floats2half2_rn(a[0], a[1]);
            __half2 p1 = __floats2half2_rn(a[2], a[3]);
            __half2* hp = (__half2*)(g_h1h + (size_t)n * 64 + 4 * ci);
            hp[0] = p0; hp[1] = p1;
            float sv = a[0] * ss[4 * ci] + a[1] * ss[4 * ci + 1]
                     + a[2] * ss[4 * ci + 2] + a[3] * ss[4 * ci + 3];
            float dv = a[0] * sd[4 * ci] + a[1] * sd[4 * ci + 1]
                     + a[2] * sd[4 * ci + 2] + a[3] * sd[4 * ci + 3];
#pragma unroll
            for (int off = 1; off <= 2; off <<= 1) {
                sv += __shfl_xor_sync(0xffffffffu, sv, off);
                dv += __shfl_xor_sync(0xffffffffu, dv, off);
            }
            if ((ci & 3) == 0) {
                int head = ci >> 2;
                ((float*)&g_as1[n])[head] = sv;
                ((float*)&g_ad1[n])[head] = dv;
            }
        }
    }
}

// ---------------- layer1 aggregation: warp per dst ----------------------------
__global__ void k_agg1(const float* __restrict__ b1, const float* __restrict__ W2,
                       const float* __restrict__ as2p, const float* __restrict__ ad2p) {
    __shared__ int   ssrc[8][32];
    __shared__ float seT[8][4][33];
    int lane = threadIdx.x & 31, w = threadIdx.x >> 5;
    int d = blockIdx.x * 8 + w;
    if (d >= NN) return;
    int base = g_rp[d];
    int deg  = g_rp[d + 1] - base;
    float4 ad = g_ad1[d];

    int hh = lane >> 3;
    float acc0 = 0.f, acc1 = 0.f;
    float d0 = 0.f, d1 = 0.f, d2 = 0.f, d3 = 0.f;

    for (int chunk = 0; chunk < deg; chunk += 32) {
        int i = chunk + lane;
        int s = 0;
        float e0 = 0.f, e1 = 0.f, e2 = 0.f, e3 = 0.f;
        if (i < deg) {
            s = g_csr[base + i];
            float4 a = g_as1[s];
            e0 = __expf(lrelu(a.x + ad.x)); d0 += e0;
            e1 = __expf(lrelu(a.y + ad.y)); d1 += e1;
            e2 = __expf(lrelu(a.z + ad.z)); d2 += e2;
            e3 = __expf(lrelu(a.w + ad.w)); d3 += e3;
        }
        __syncwarp();
        ssrc[w][lane] = s;
        seT[w][0][lane] = e0; seT[w][1][lane] = e1;
        seT[w][2][lane] = e2; seT[w][3][lane] = e3;
        __syncwarp();
        int cnt = deg - chunk; if (cnt > 32) cnt = 32;
        int j = 0;
        for (; j + 8 <= cnt; j += 8) {
            __half2 v[8]; float ew[8];
#pragma unroll
            for (int k = 0; k < 8; k++) {
                int sj = ssrc[w][j + k];
                v[k]  = ((const __half2*)(g_h1h + (size_t)sj * 64))[lane];
                ew[k] = seT[w][hh][j + k];
            }
#pragma unroll
            for (int k = 0; k < 8; k++) {
                float2 f = __half22float2(v[k]);
                acc0 = fmaf(f.x, ew[k], acc0);
                acc1 = fmaf(f.y, ew[k], acc1);
            }
        }
        for (; j < cnt; j++) {
            int sj = ssrc[w][j];
            __half2 vv = ((const __half2*)(g_h1h + (size_t)sj * 64))[lane];
            float ew = seT[w][hh][j];
            float2 f = __half22float2(vv);
            acc0 = fmaf(f.x, ew, acc0);
            acc1 = fmaf(f.y, ew, acc1);
        }
    }
#pragma unroll
    for (int off = 16; off; off >>= 1) {
        d0 += __shfl_xor_sync(0xffffffffu, d0, off);
        d1 += __shfl_xor_sync(0xffffffffu, d1, off);
        d2 += __shfl_xor_sync(0xffffffffu, d2, off);
        d3 += __shfl_xor_sync(0xffffffffu, d3, off);
    }

    float den = (hh == 0 ? d0 : hh == 1 ? d1 : hh == 2 ? d2 : d3) + EPSV;
    float2 bb = ((const float2*)b1)[lane];
    float2 ww = ((const float2*)W2)[lane];
    float v0 = acc0 / den + bb.x;
    float v1 = acc1 / den + bb.y;
    v0 = v0 > 0.f ? v0 : (__expf(v0) - 1.f);
    v1 = v1 > 0.f ? v1 : (__expf(v1) - 1.f);
    float h2 = v0 * ww.x + v1 * ww.y;
#pragma unroll
    for (int off = 16; off; off >>= 1) h2 += __shfl_xor_sync(0xffffffffu, h2, off);
    if (lane == 0) {
        g_sh2[d] = make_float2(h2 * as2p[0], h2);
        g_ad2[d] = h2 * ad2p[0];
    }
}

// ---------------- layer2 aggregation + final output ---------------------------
__global__ void k_agg2(float* __restrict__ out, const float* __restrict__ b2) {
    int lane = threadIdx.x & 31, warp = threadIdx.x >> 5;
    int d = blockIdx.x * 8 + warp;
    if (d >= NN) return;
    int base = g_rp[d];
    int deg  = g_rp[d + 1] - base;
    float adv = g_ad2[d];

    float num = 0.f, den = 0.f;
    for (int i = lane; i < deg; i += 32) {
        int s = g_csr[base + i];
        float2 sh = g_sh2[s];
        float e = __expf(lrelu(sh.x + adv));
        num = fmaf(e, sh.y, num);
        den += e;
    }
#pragma unroll
    for (int off = 16; off; off >>= 1) {
        num += __shfl_xor_sync(0xffffffffu, num, off);
        den += __shfl_xor_sync(0xffffffffu, den, off);
    }
    if (lane == 0) out[d] = num / (den + EPSV) + b2[0];
}

// ---------------- launch: fork gemm1 onto a side stream -----------------------
extern "C" void kernel_launch(void* const* d_in, const int* in_sizes, int n_in,
                              void* d_out, int out_size) {
    const float* x    = (const float*)d_in[0];
    const int*   ei   = (const int*)d_in[1];
    const float* W1   = (const float*)d_in[2];
    const float* as1  = (const float*)d_in[3];
    const float* ad1  = (const float*)d_in[4];
    const float* b1   = (const float*)d_in[5];
    const float* W2   = (const float*)d_in[6];
    const float* as2  = (const float*)d_in[7];
    const float* ad2  = (const float*)d_in[8];
    const float* b2   = (const float*)d_in[9];
    float*       out  = (float*)d_out;

    int E    = in_sizes[1] / 2;
    int etot = E + NN;
    int eb4  = (E / 4 + 255) / 256;

    // Fork: gemm1 on s2 concurrently with the CSR chain on the null stream.
    // Streams/events created per call and intentionally not destroyed
    // (kernel_launch runs exactly twice; destroying a capturing stream is illegal).
    cudaStream_t s2;
    cudaStreamCreate(&s2);
    cudaEvent_t eF, eG;
    cudaEventCreateWithFlags(&eF, cudaEventDisableTiming);
    cudaEventCreateWithFlags(&eG, cudaEventDisableTiming);

    cudaEventRecord(eF, 0);
    cudaStreamWaitEvent(s2, eF, 0);
    k_gemm1<<<GEMM_BLOCKS, 256, 0, s2>>>(x, W1, as1, ad1);
    cudaEventRecord(eG, s2);

    k_hist   <<<eb4, 256>>>(ei, E);
    k_rpf    <<<NB, 1024>>>(etot);
    k_scatter<<<eb4, 256>>>(ei, E);

    cudaStreamWaitEvent(0, eG, 0);
    k_agg1   <<<NN / 8, 256>>>(b1, W2, as2, ad2);
    k_agg2   <<<NN / 8, 256>>>(out, b2);
}